// round 8
// baseline (speedup 1.0000x reference)
#include <cuda_runtime.h>
#include <cuda_fp16.h>
#include <cstdint>
#include <math.h>

#define BATCH 16
#define SEQ   1024
#define EDIM  512
#define NROWS (BATCH*SEQ)
#define TOTALD ((double)BATCH*SEQ*SEQ)
#define TEMP  13.544f
#define EPSV  1e-5

// ---------------- device scratch (no allocations allowed) ------------------
__device__ __half g_h[(size_t)NROWS * EDIM];   // 16 MB fp16 copy of x
__device__ float  g_sq[NROWS];
__device__ double g_sum;
__device__ double g_sumsq;

// ---------------- PTX helpers ----------------------------------------------
__device__ __forceinline__ uint32_t smem_u32(const void* p) {
    uint32_t a;
    asm("{ .reg .u64 t; cvta.to.shared.u64 t, %1; cvt.u32.u64 %0, t; }" : "=r"(a) : "l"(p));
    return a;
}
__device__ __forceinline__ void cp16(uint32_t dst, const void* src) {
    asm volatile("cp.async.cg.shared.global [%0], [%1], 16;" :: "r"(dst), "l"(src));
}
#define CP_COMMIT() asm volatile("cp.async.commit_group;" ::: "memory")
#define CP_WAIT(n)  asm volatile("cp.async.wait_group %0;" :: "n"(n) : "memory")

__device__ __forceinline__ void ldm4(uint32_t* r, uint32_t addr) {
    asm volatile("ldmatrix.sync.aligned.m8n8.x4.shared.b16 {%0,%1,%2,%3}, [%4];"
                 : "=r"(r[0]), "=r"(r[1]), "=r"(r[2]), "=r"(r[3]) : "r"(addr));
}
__device__ __forceinline__ void mma16816(float* c, const uint32_t* a,
                                         uint32_t b0, uint32_t b1) {
    asm volatile("mma.sync.aligned.m16n8k16.row.col.f32.f16.f16.f32 "
                 "{%0,%1,%2,%3}, {%4,%5,%6,%7}, {%8,%9}, {%0,%1,%2,%3};"
                 : "+f"(c[0]), "+f"(c[1]), "+f"(c[2]), "+f"(c[3])
                 : "r"(a[0]), "r"(a[1]), "r"(a[2]), "r"(a[3]), "r"(b0), "r"(b1));
}

// ---------------- gram geometry (round-6 winner) ---------------------------
#define KC        32
#define NCHUNK    (EDIM / KC)              // 16
#define TROWB     80
#define TILE_B    (128 * TROWB)            // 10240
#define NTILES    2                        // A, B
#define BUF_B     (NTILES * TILE_B)        // 20480
#define SM_SQA    0
#define SM_SQB    512
#define SM_RED    1024
#define SM_REDQ   1056
#define SM_TILES  2048
#define TRPAD     129                      // staging 128*129*4 = 66048
#define GRAM_SMEM (SM_TILES + 128 * TRPAD * 4)   // 68096

// ---------------------------------------------------------------------------
// Kernel 1: fp32 -> fp16 + per-row squared norms (fp32).
// ---------------------------------------------------------------------------
__global__ __launch_bounds__(256)
void conv_kernel(const float* __restrict__ x) {
    if (blockIdx.x == 0 && threadIdx.x == 0) { g_sum = 0.0; g_sumsq = 0.0; }
    int gw   = (blockIdx.x * blockDim.x + threadIdx.x) >> 5;
    int lane = threadIdx.x & 31;
    if (gw >= NROWS) return;
    const float4* row = (const float4*)(x + (size_t)gw * EDIM);
    __half2* hp = (__half2*)(g_h + (size_t)gw * EDIM);
    float s = 0.f;
    #pragma unroll
    for (int i = 0; i < 4; i++) {
        int e = lane + 32 * i;
        float4 v = row[e];
        s += v.x*v.x + v.y*v.y + v.z*v.z + v.w*v.w;
        hp[e * 2]     = __floats2half2_rn(v.x, v.y);
        hp[e * 2 + 1] = __floats2half2_rn(v.z, v.w);
    }
    #pragma unroll
    for (int o = 16; o > 0; o >>= 1) s += __shfl_xor_sync(0xffffffffu, s, o);
    if (lane == 0) g_sq[gw] = s;
}

// ---------------------------------------------------------------------------
// Kernel 2: symmetric fp16 Gram, upper-triangle tile pairs.
// 128 threads / 4 warps of 64x64, 2-stage cp.async, 2 CTAs/SM.
// (Exact round-6 mainloop — do not restructure; two restructure attempts
//  both regressed.)
// ---------------------------------------------------------------------------
__device__ __forceinline__ void prefetch_chunk(
    const __half* A, const __half* B, uint32_t sb, int buf, int kc, int tid)
{
    const __half* panels[NTILES] = { A, B };
    int p = tid >> 6, s = tid & 63;          // 64 threads per panel
    const char* src = (const char*)panels[p] + kc * (KC * 2);
    uint32_t tb = sb + SM_TILES + buf * BUF_B + p * TILE_B;
    #pragma unroll
    for (int i = 0; i < 8; i++) {
        int idx = i * 64 + s;                // 0..511 (16B granules)
        int row = idx >> 2;
        int q   = idx & 3;
        cp16(tb + row * TROWB + q * 16,
             src + (size_t)row * (EDIM * 2) + q * 16);
    }
}

__global__ __launch_bounds__(128, 2)
void gram_tc_kernel(float* __restrict__ dout) {
    extern __shared__ char smem[];
    const uint32_t sb = smem_u32(smem);
    const int tid  = threadIdx.x;
    const int wid  = tid >> 5;
    const int lane = tid & 31;

    // decode upper-triangle tile pair (8x8 tiles, 36 pairs)
    int p = blockIdx.x, ti = 0;
    while (p >= 8 - ti) { p -= 8 - ti; ti++; }
    const int tj   = ti + p;
    const int b    = blockIdx.z;
    const int row0 = ti * 128;
    const int col0 = tj * 128;
    const int warp_m = (wid >> 1) * 64;
    const int warp_n = (wid & 1) * 64;

    const __half* A = g_h + ((size_t)(b * SEQ + row0)) * EDIM;
    const __half* B = g_h + ((size_t)(b * SEQ + col0)) * EDIM;

    if (tid < 128) {
        ((float*)(smem + SM_SQA))[tid] = g_sq[b * SEQ + row0 + tid];
        ((float*)(smem + SM_SQB))[tid] = g_sq[b * SEQ + col0 + tid];
    }

    float acc[4][8][4];
    #pragma unroll
    for (int mi = 0; mi < 4; mi++)
        #pragma unroll
        for (int ni = 0; ni < 8; ni++)
            #pragma unroll
            for (int k = 0; k < 4; k++) acc[mi][ni][k] = 0.f;

    const uint32_t aOff = (uint32_t)((warp_m + (lane & 15)) * TROWB + (lane >> 4) * 16);
    const uint32_t bOff = (uint32_t)((warp_n + (lane & 7) + ((lane >> 4) << 3)) * TROWB
                                     + ((lane >> 3) & 1) * 16);

    prefetch_chunk(A, B, sb, 0, 0, tid);
    CP_COMMIT();

    #pragma unroll 1
    for (int c = 0; c < NCHUNK; c++) {
        if (c + 1 < NCHUNK) {
            prefetch_chunk(A, B, sb, (c + 1) & 1, c + 1, tid);
            CP_COMMIT();
            CP_WAIT(1);
        } else {
            CP_WAIT(0);
        }
        __syncthreads();

        uint32_t base = sb + SM_TILES + (c & 1) * BUF_B;
        #pragma unroll
        for (int ks = 0; ks < 2; ks++) {
            const uint32_t kb = ks * 32;
            uint32_t aF[16], bb[16];
            #pragma unroll
            for (int mi = 0; mi < 4; mi++)
                ldm4(&aF[mi * 4], base + 0 * TILE_B + aOff + mi * 16 * TROWB + kb);
            #pragma unroll
            for (int nj = 0; nj < 4; nj++)
                ldm4(&bb[nj * 4], base + 1 * TILE_B + bOff + nj * 16 * TROWB + kb);
            #pragma unroll
            for (int mi = 0; mi < 4; mi++)
                #pragma unroll
                for (int ni = 0; ni < 8; ni++)
                    mma16816(acc[mi][ni], &aF[mi * 4], bb[ni * 2], bb[ni * 2 + 1]);
        }
        __syncthreads();
    }

    // ---------------- epilogue -------------------------------------------
    const int g  = lane >> 2;
    const int t4 = lane & 3;
    const float* sqA = (const float*)(smem + SM_SQA);
    const float* sqB = (const float*)(smem + SM_SQB);
    float* trb = (float*)(smem + SM_TILES);
    float* Db  = dout + (size_t)b * SEQ * SEQ;
    const bool diag = (ti == tj);
    float fsum = 0.f, fsq = 0.f;
    #pragma unroll
    for (int mi = 0; mi < 4; mi++) {
        #pragma unroll
        for (int h = 0; h < 2; h++) {
            int rl = warp_m + mi * 16 + g + h * 8;
            float sr = sqA[rl];
            float* rp = Db + (size_t)(row0 + rl) * SEQ + col0;
            #pragma unroll
            for (int ni = 0; ni < 8; ni++) {
                int cl = warp_n + ni * 8 + t4 * 2;
                float d0 = fmaxf(sr + sqB[cl]     - 2.f * acc[mi][ni][2 * h],     0.f);
                float d1 = fmaxf(sr + sqB[cl + 1] - 2.f * acc[mi][ni][2 * h + 1], 0.f);
                if (diag) {                    // exact-zero self distance
                    if (rl == cl)     d0 = 0.f;
                    if (rl == cl + 1) d1 = 0.f;
                }
                fsum += d0 + d1;
                fsq  += d0 * d0 + d1 * d1;
                float2 o; o.x = d0; o.y = d1;
                *(float2*)(rp + cl) = o;
                trb[rl * TRPAD + cl]     = d0;
                trb[rl * TRPAD + cl + 1] = d1;
            }
        }
    }

    if (!diag) {
        __syncthreads();   // trb fully written
        int cc = tid;
        float* op = Db + (size_t)(col0 + cc) * SEQ + row0;
        #pragma unroll
        for (int i = 0; i < 128; i += 4) {
            float4 v;
            v.x = trb[(i + 0) * TRPAD + cc];
            v.y = trb[(i + 1) * TRPAD + cc];
            v.z = trb[(i + 2) * TRPAD + cc];
            v.w = trb[(i + 3) * TRPAD + cc];
            *(float4*)(op + i) = v;
        }
        fsum *= 2.f; fsq *= 2.f;
    }

    // stats reduction
    #pragma unroll
    for (int o = 16; o > 0; o >>= 1) {
        fsum += __shfl_xor_sync(0xffffffffu, fsum, o);
        fsq  += __shfl_xor_sync(0xffffffffu, fsq,  o);
    }
    if (lane == 0) {
        ((double*)(smem + SM_RED))[wid]  = (double)fsum;
        ((double*)(smem + SM_REDQ))[wid] = (double)fsq;
    }
    __syncthreads();
    if (tid == 0) {
        double s = 0.0, q = 0.0;
        #pragma unroll
        for (int k = 0; k < 4; k++) {
            s += ((double*)(smem + SM_RED))[k];
            q += ((double*)(smem + SM_REDQ))[k];
        }
        atomicAdd(&g_sum, s);
        atomicAdd(&g_sumsq, q);
    }
}

// ---------------------------------------------------------------------------
// Kernel 3: warp-per-row softmax, in place. coef from global stats (no
// finalize kernel). Row max analytically 0 when coef <= 0 (d_ii = 0 in
// every row); guarded full reduction otherwise.
// ---------------------------------------------------------------------------
__global__ __launch_bounds__(256)
void softmax_kernel(float* __restrict__ dout, const float* __restrict__ gamma) {
    const int wid  = threadIdx.x >> 5;
    const int lane = threadIdx.x & 31;
    const size_t row = (size_t)blockIdx.x * 8 + wid;
    float4* rp = (float4*)(dout + row * SEQ);

    double mean = g_sum / TOTALD;
    double var  = g_sumsq / TOTALD - mean * mean;
    const float coef = (float)(-(double)gamma[0] / (sqrt(var + EPSV) * (double)TEMP));

    float4 v[8];
    #pragma unroll
    for (int i = 0; i < 8; i++) v[i] = rp[lane + 32 * i];

    float m = 0.f;
    if (coef > 0.f) {            // not taken for gamma>0; correctness guard
        m = -1e30f;
        #pragma unroll
        for (int i = 0; i < 8; i++)
            m = fmaxf(m, fmaxf(fmaxf(v[i].x, v[i].y), fmaxf(v[i].z, v[i].w)));
        #pragma unroll
        for (int o = 16; o > 0; o >>= 1) m = fmaxf(m, __shfl_xor_sync(0xffffffffu, m, o));
        m *= coef;
    }

    float s = 0.f;
    #pragma unroll
    for (int i = 0; i < 8; i++) {
        v[i].x = __expf(coef * v[i].x - m); v[i].y = __expf(coef * v[i].y - m);
        v[i].z = __expf(coef * v[i].z - m); v[i].w = __expf(coef * v[i].w - m);
        s += (v[i].x + v[i].y) + (v[i].z + v[i].w);
    }
    #pragma unroll
    for (int o = 16; o > 0; o >>= 1) s += __shfl_xor_sync(0xffffffffu, s, o);
    const float inv = 1.f / s;

    #pragma unroll
    for (int i = 0; i < 8; i++) {
        v[i].x *= inv; v[i].y *= inv; v[i].z *= inv; v[i].w *= inv;
        rp[lane + 32 * i] = v[i];
    }
}

// ---------------------------------------------------------------------------
extern "C" void kernel_launch(void* const* d_in, const int* in_sizes, int n_in,
                              void* d_out, int out_size) {
    const float* x     = (const float*)d_in[0];
    const float* gamma = (const float*)d_in[1];
    float* out = (float*)d_out;

    cudaFuncSetAttribute(gram_tc_kernel,
                         cudaFuncAttributeMaxDynamicSharedMemorySize, GRAM_SMEM);

    conv_kernel<<<NROWS * 32 / 256, 256>>>(x);
    dim3 grid(36, 1, BATCH);
    gram_tc_kernel<<<grid, 128, GRAM_SMEM>>>(out);
    softmax_kernel<<<NROWS / 8, 256>>>(out, gamma);
}

// round 9
// speedup vs baseline: 1.1893x; 1.1893x over previous
#include <cuda_runtime.h>
#include <cuda_fp16.h>
#include <cstdint>
#include <math.h>

#define BATCH 16
#define SEQ   1024
#define EDIM  512
#define NROWS (BATCH*SEQ)
#define TOTALF ((float)((double)BATCH*SEQ*SEQ))
#define TEMP  13.544f
#define EPSV  1e-5f

// ---------------- device scratch (no allocations allowed) ------------------
__device__ __half g_h[(size_t)NROWS * EDIM];   // 16 MB fp16 copy of x
__device__ float  g_sq[NROWS];
__device__ double g_sum;
__device__ double g_sumsq;

// ---------------- PTX helpers ----------------------------------------------
__device__ __forceinline__ uint32_t smem_u32(const void* p) {
    uint32_t a;
    asm("{ .reg .u64 t; cvta.to.shared.u64 t, %1; cvt.u32.u64 %0, t; }" : "=r"(a) : "l"(p));
    return a;
}
__device__ __forceinline__ void cp16(uint32_t dst, const void* src) {
    asm volatile("cp.async.cg.shared.global [%0], [%1], 16;" :: "r"(dst), "l"(src));
}
#define CP_COMMIT() asm volatile("cp.async.commit_group;" ::: "memory")
#define CP_WAIT(n)  asm volatile("cp.async.wait_group %0;" :: "n"(n) : "memory")

__device__ __forceinline__ void ldm4(uint32_t* r, uint32_t addr) {
    asm volatile("ldmatrix.sync.aligned.m8n8.x4.shared.b16 {%0,%1,%2,%3}, [%4];"
                 : "=r"(r[0]), "=r"(r[1]), "=r"(r[2]), "=r"(r[3]) : "r"(addr));
}
__device__ __forceinline__ void mma16816(float* c, const uint32_t* a,
                                         uint32_t b0, uint32_t b1) {
    asm volatile("mma.sync.aligned.m16n8k16.row.col.f32.f16.f16.f32 "
                 "{%0,%1,%2,%3}, {%4,%5,%6,%7}, {%8,%9}, {%0,%1,%2,%3};"
                 : "+f"(c[0]), "+f"(c[1]), "+f"(c[2]), "+f"(c[3])
                 : "r"(a[0]), "r"(a[1]), "r"(a[2]), "r"(a[3]), "r"(b0), "r"(b1));
}

// ---------------- gram geometry (round-6 winner) ---------------------------
#define KC        32
#define NCHUNK    (EDIM / KC)              // 16
#define TROWB     80
#define TILE_B    (128 * TROWB)            // 10240
#define NTILES    2                        // A, B
#define BUF_B     (NTILES * TILE_B)        // 20480
#define SM_SQA    0
#define SM_SQB    512
#define SM_RED    1024
#define SM_REDQ   1056
#define SM_TILES  2048
#define TRPAD     129                      // staging 128*129*4 = 66048
#define GRAM_SMEM (SM_TILES + 128 * TRPAD * 4)   // 68096

// ---------------------------------------------------------------------------
// Kernel 1: fp32 -> fp16 + per-row squared norms. Each thread converts 8
// contiguous floats per iteration -> one 16B store.
// ---------------------------------------------------------------------------
__global__ __launch_bounds__(256)
void conv_kernel(const float* __restrict__ x) {
    if (blockIdx.x == 0 && threadIdx.x == 0) { g_sum = 0.0; g_sumsq = 0.0; }
    int gw   = (blockIdx.x * blockDim.x + threadIdx.x) >> 5;
    int lane = threadIdx.x & 31;
    if (gw >= NROWS) return;
    const float4* row = (const float4*)(x + (size_t)gw * EDIM);
    uint4* op = (uint4*)(g_h + (size_t)gw * EDIM);   // 64 uint4 per row
    float s = 0.f;
    #pragma unroll
    for (int p = 0; p < 2; p++) {
        int u = lane + 32 * p;               // output uint4 index 0..63
        float4 a = row[2 * u];
        float4 b = row[2 * u + 1];
        s += a.x*a.x + a.y*a.y + a.z*a.z + a.w*a.w;
        s += b.x*b.x + b.y*b.y + b.z*b.z + b.w*b.w;
        __half2 h[4];
        h[0] = __floats2half2_rn(a.x, a.y);
        h[1] = __floats2half2_rn(a.z, a.w);
        h[2] = __floats2half2_rn(b.x, b.y);
        h[3] = __floats2half2_rn(b.z, b.w);
        op[u] = *(uint4*)h;
    }
    #pragma unroll
    for (int o = 16; o > 0; o >>= 1) s += __shfl_xor_sync(0xffffffffu, s, o);
    if (lane == 0) g_sq[gw] = s;
}

// ---------------------------------------------------------------------------
// Kernel 2: symmetric fp16 Gram, upper-triangle tile pairs.
// 128 threads / 4 warps of 64x64, 2-stage cp.async, 2 CTAs/SM.
// (Round-6 mainloop, byte-for-byte. Do not restructure.)
// ---------------------------------------------------------------------------
__device__ __forceinline__ void prefetch_chunk(
    const __half* A, const __half* B, uint32_t sb, int buf, int kc, int tid)
{
    const __half* panels[NTILES] = { A, B };
    int p = tid >> 6, s = tid & 63;          // 64 threads per panel
    const char* src = (const char*)panels[p] + kc * (KC * 2);
    uint32_t tb = sb + SM_TILES + buf * BUF_B + p * TILE_B;
    #pragma unroll
    for (int i = 0; i < 8; i++) {
        int idx = i * 64 + s;                // 0..511 (16B granules)
        int row = idx >> 2;
        int q   = idx & 3;
        cp16(tb + row * TROWB + q * 16,
             src + (size_t)row * (EDIM * 2) + q * 16);
    }
}

__global__ __launch_bounds__(128, 2)
void gram_tc_kernel(float* __restrict__ dout) {
    extern __shared__ char smem[];
    const uint32_t sb = smem_u32(smem);
    const int tid  = threadIdx.x;
    const int wid  = tid >> 5;
    const int lane = tid & 31;

    // decode upper-triangle tile pair (8x8 tiles, 36 pairs)
    int p = blockIdx.x, ti = 0;
    while (p >= 8 - ti) { p -= 8 - ti; ti++; }
    const int tj   = ti + p;
    const int b    = blockIdx.z;
    const int row0 = ti * 128;
    const int col0 = tj * 128;
    const int warp_m = (wid >> 1) * 64;
    const int warp_n = (wid & 1) * 64;

    const __half* A = g_h + ((size_t)(b * SEQ + row0)) * EDIM;
    const __half* B = g_h + ((size_t)(b * SEQ + col0)) * EDIM;

    if (tid < 128) {
        ((float*)(smem + SM_SQA))[tid] = g_sq[b * SEQ + row0 + tid];
        ((float*)(smem + SM_SQB))[tid] = g_sq[b * SEQ + col0 + tid];
    }

    float acc[4][8][4];
    #pragma unroll
    for (int mi = 0; mi < 4; mi++)
        #pragma unroll
        for (int ni = 0; ni < 8; ni++)
            #pragma unroll
            for (int k = 0; k < 4; k++) acc[mi][ni][k] = 0.f;

    const uint32_t aOff = (uint32_t)((warp_m + (lane & 15)) * TROWB + (lane >> 4) * 16);
    const uint32_t bOff = (uint32_t)((warp_n + (lane & 7) + ((lane >> 4) << 3)) * TROWB
                                     + ((lane >> 3) & 1) * 16);

    prefetch_chunk(A, B, sb, 0, 0, tid);
    CP_COMMIT();

    #pragma unroll 1
    for (int c = 0; c < NCHUNK; c++) {
        if (c + 1 < NCHUNK) {
            prefetch_chunk(A, B, sb, (c + 1) & 1, c + 1, tid);
            CP_COMMIT();
            CP_WAIT(1);
        } else {
            CP_WAIT(0);
        }
        __syncthreads();

        uint32_t base = sb + SM_TILES + (c & 1) * BUF_B;
        #pragma unroll
        for (int ks = 0; ks < 2; ks++) {
            const uint32_t kb = ks * 32;
            uint32_t aF[16], bb[16];
            #pragma unroll
            for (int mi = 0; mi < 4; mi++)
                ldm4(&aF[mi * 4], base + 0 * TILE_B + aOff + mi * 16 * TROWB + kb);
            #pragma unroll
            for (int nj = 0; nj < 4; nj++)
                ldm4(&bb[nj * 4], base + 1 * TILE_B + bOff + nj * 16 * TROWB + kb);
            #pragma unroll
            for (int mi = 0; mi < 4; mi++)
                #pragma unroll
                for (int ni = 0; ni < 8; ni++)
                    mma16816(acc[mi][ni], &aF[mi * 4], bb[ni * 2], bb[ni * 2 + 1]);
        }
        __syncthreads();
    }

    // ---------------- epilogue -------------------------------------------
    const int g  = lane >> 2;
    const int t4 = lane & 3;
    const float* sqA = (const float*)(smem + SM_SQA);
    const float* sqB = (const float*)(smem + SM_SQB);
    float* trb = (float*)(smem + SM_TILES);
    float* Db  = dout + (size_t)b * SEQ * SEQ;
    const bool diag = (ti == tj);
    float fsum = 0.f, fsq = 0.f;
    #pragma unroll
    for (int mi = 0; mi < 4; mi++) {
        #pragma unroll
        for (int h = 0; h < 2; h++) {
            int rl = warp_m + mi * 16 + g + h * 8;
            float sr = sqA[rl];
            float* rp = Db + (size_t)(row0 + rl) * SEQ + col0;
            #pragma unroll
            for (int ni = 0; ni < 8; ni++) {
                int cl = warp_n + ni * 8 + t4 * 2;
                float d0 = fmaxf(sr + sqB[cl]     - 2.f * acc[mi][ni][2 * h],     0.f);
                float d1 = fmaxf(sr + sqB[cl + 1] - 2.f * acc[mi][ni][2 * h + 1], 0.f);
                if (diag) {                    // exact-zero self distance
                    if (rl == cl)     d0 = 0.f;
                    if (rl == cl + 1) d1 = 0.f;
                }
                fsum += d0 + d1;
                fsq  += d0 * d0 + d1 * d1;
                float2 o; o.x = d0; o.y = d1;
                *(float2*)(rp + cl) = o;
                trb[rl * TRPAD + cl]     = d0;
                trb[rl * TRPAD + cl + 1] = d1;
            }
        }
    }

    if (!diag) {
        __syncthreads();   // trb fully written
        int cc = tid;
        float* op = Db + (size_t)(col0 + cc) * SEQ + row0;
        #pragma unroll
        for (int i = 0; i < 128; i += 4) {
            float4 v;
            v.x = trb[(i + 0) * TRPAD + cc];
            v.y = trb[(i + 1) * TRPAD + cc];
            v.z = trb[(i + 2) * TRPAD + cc];
            v.w = trb[(i + 3) * TRPAD + cc];
            *(float4*)(op + i) = v;
        }
        fsum *= 2.f; fsq *= 2.f;
    }

    // stats reduction
    #pragma unroll
    for (int o = 16; o > 0; o >>= 1) {
        fsum += __shfl_xor_sync(0xffffffffu, fsum, o);
        fsq  += __shfl_xor_sync(0xffffffffu, fsq,  o);
    }
    if (lane == 0) {
        ((double*)(smem + SM_RED))[wid]  = (double)fsum;
        ((double*)(smem + SM_REDQ))[wid] = (double)fsq;
    }
    __syncthreads();
    if (tid == 0) {
        double s = 0.0, q = 0.0;
        #pragma unroll
        for (int k = 0; k < 4; k++) {
            s += ((double*)(smem + SM_RED))[k];
            q += ((double*)(smem + SM_REDQ))[k];
        }
        atomicAdd(&g_sum, s);
        atomicAdd(&g_sumsq, q);
    }
}

// ---------------------------------------------------------------------------
// Kernel 3: warp-per-row softmax, in place. coef from global stats computed
// in FLOAT (fp64 div/sqrt per thread cost ~10us in rounds 7/8 — never again).
// Row max analytically 0 when coef <= 0 (d_ii = 0 in every row).
// ---------------------------------------------------------------------------
__global__ __launch_bounds__(256)
void softmax_kernel(float* __restrict__ dout, const float* __restrict__ gamma) {
    const int wid  = threadIdx.x >> 5;
    const int lane = threadIdx.x & 31;
    const size_t row = (size_t)blockIdx.x * 8 + wid;
    float4* rp = (float4*)(dout + row * SEQ);

    const float fsum = (float)g_sum;       // double -> float convert only
    const float fssq = (float)g_sumsq;
    const float mean = fsum * (1.f / TOTALF);
    const float var  = fssq * (1.f / TOTALF) - mean * mean;
    const float coef = -gamma[0] * rsqrtf(var + EPSV) * (1.f / TEMP);

    float4 v[8];
    #pragma unroll
    for (int i = 0; i < 8; i++) v[i] = rp[lane + 32 * i];

    float m = 0.f;
    if (coef > 0.f) {            // not taken for gamma>0; correctness guard
        m = -1e30f;
        #pragma unroll
        for (int i = 0; i < 8; i++)
            m = fmaxf(m, fmaxf(fmaxf(v[i].x, v[i].y), fmaxf(v[i].z, v[i].w)));
        #pragma unroll
        for (int o = 16; o > 0; o >>= 1) m = fmaxf(m, __shfl_xor_sync(0xffffffffu, m, o));
        m *= coef;
    }

    float s = 0.f;
    #pragma unroll
    for (int i = 0; i < 8; i++) {
        v[i].x = __expf(coef * v[i].x - m); v[i].y = __expf(coef * v[i].y - m);
        v[i].z = __expf(coef * v[i].z - m); v[i].w = __expf(coef * v[i].w - m);
        s += (v[i].x + v[i].y) + (v[i].z + v[i].w);
    }
    #pragma unroll
    for (int o = 16; o > 0; o >>= 1) s += __shfl_xor_sync(0xffffffffu, s, o);
    const float inv = 1.f / s;

    #pragma unroll
    for (int i = 0; i < 8; i++) {
        v[i].x *= inv; v[i].y *= inv; v[i].z *= inv; v[i].w *= inv;
        rp[lane + 32 * i] = v[i];
    }
}

// ---------------------------------------------------------------------------
extern "C" void kernel_launch(void* const* d_in, const int* in_sizes, int n_in,
                              void* d_out, int out_size) {
    const float* x     = (const float*)d_in[0];
    const float* gamma = (const float*)d_in[1];
    float* out = (float*)d_out;

    cudaFuncSetAttribute(gram_tc_kernel,
                         cudaFuncAttributeMaxDynamicSharedMemorySize, GRAM_SMEM);

    conv_kernel<<<NROWS * 32 / 256, 256>>>(x);
    dim3 grid(36, 1, BATCH);
    gram_tc_kernel<<<grid, 128, GRAM_SMEM>>>(out);
    softmax_kernel<<<NROWS / 8, 256>>>(out, gamma);
}